// round 14
// baseline (speedup 1.0000x reference)
#include <cuda_runtime.h>
#include <cuda_bf16.h>
#include <math.h>
#include <stdint.h>

#define BB    8
#define N1    2048
#define N2    8192
#define C1    256
#define C2    128
#define CIN   384
#define MOUT  256
#define NTOT  (BB*N2)      // 65536 columns
#define BNCOL 64           // GEMM block N
#define NBLK  (NTOT/BNCOL) // 1024 GEMM blocks
#define NCH1  (CIN/16)     // 24 k16-chunks
#define NCH2  (MOUT/16)    // 16 k16-chunks

// pipeline geometry
#define PSTAGES   3
#define W_STAGE   20480                        // 256 rows x 80B
#define X_STAGE   4096                         // 64 cols x 64B (swizzled)
#define WOFF      0
#define XOFF      (PSTAGES*W_STAGE)            // 61440
#define MBOFF     (XOFF + PSTAGES*X_STAGE)     // 73728
#define SMEM_DYN  (MBOFF + 64)

// ---------------- scratch (static __device__; no allocation) ----------------
__device__ int    g_idx[BB*N2*3];
__device__ float  g_wgt[BB*N2*3];
__device__ float  g_Y1[(size_t)BB*MOUT*N2];     // 67 MB raw layer-1 out
__device__ float  g_scale1[MOUT], g_shift1[MOUT];
__device__ float  g_scale2[MOUT], g_shift2[MOUT];
__device__ float2 g_bpart[(size_t)NBLK*MOUT];
// packed X images: [b][chunk][n][16 u32]; kpair-permuted + SW128-swizzled.
// Columns with (n&2) store hi half at +32 / lo at +0 ("flip") so that LDS.64
// bank-pair sets of the 4 columns per 16-lane phase are disjoint.
__device__ __align__(128) unsigned char g_Xim1[(size_t)BB*NCH1*N2*64]; // 100 MB
__device__ __align__(128) unsigned char g_Xim2[(size_t)BB*NCH2*N2*64]; //  67 MB
// pre-baked W smem images (bf16 hi/lo per 16-k chunk):
// row m = 40 uint16: [0..15]=hi bf16, [16..31]=lo bf16, [32..39]=pad
__device__ __align__(128) unsigned short g_W1img[NCH1*256*40];
__device__ __align__(128) unsigned short g_W2img[NCH2*256*40];

__device__ __forceinline__ uint32_t pack_bf16(float lo, float hi)
{
    uint32_t r;
    asm volatile("cvt.rn.bf16x2.f32 %0, %1, %2;" : "=r"(r) : "f"(hi), "f"(lo));
    return r;
}
__device__ __forceinline__ float bflo_f(uint32_t p) { return __uint_as_float(p << 16); }
__device__ __forceinline__ float bfhi_f(uint32_t p) { return __uint_as_float(p & 0xFFFF0000u); }
__device__ __host__ __forceinline__ uint32_t swz(uint32_t A) { return A ^ ((A >> 3) & 0x70); }

// ---------------- 1) three_nn (3-FFMA distance) ------------------------------
__global__ void knn_kernel(const float* __restrict__ xyz2,
                           const float* __restrict__ xyz1)
{
    __shared__ float sx[N1], sy[N1], sz[N1], sq[N1];
    const int b = blockIdx.y;
    const float* p1 = xyz1 + (size_t)b * 3 * N1;
    for (int t = threadIdx.x; t < N1; t += blockDim.x) {
        const float x = p1[t], y = p1[N1 + t], z = p1[2*N1 + t];
        sx[t] = -2.0f * x; sy[t] = -2.0f * y; sz[t] = -2.0f * z;
        sq[t] = x*x + y*y + z*z;
    }
    __syncthreads();

    const int n = blockIdx.x * blockDim.x + threadIdx.x;
    const float* p2 = xyz2 + (size_t)b * 3 * N2;
    const float px = p2[n], py = p2[N2 + n], pz = p2[2*N2 + n];
    const float pq = px*px + py*py + pz*pz;

    float d0 = 3.4e38f, d1 = 3.4e38f, d2v = 3.4e38f;
    int   i0 = 0, i1 = 0, i2 = 0;
    #pragma unroll 4
    for (int j = 0; j < N1; ++j) {
        const float d = fmaf(px, sx[j], fmaf(py, sy[j], fmaf(pz, sz[j], sq[j])));
        if (d < d2v) {
            if (d < d1) {
                d2v = d1; i2 = i1;
                if (d < d0) { d1 = d0; i1 = i0; d0 = d; i0 = j; }
                else        { d1 = d;  i1 = j; }
            } else { d2v = d; i2 = j; }
        }
    }
    d0  = fmaxf(d0  + pq, 1e-10f);
    d1  = fmaxf(d1  + pq, 1e-10f);
    d2v = fmaxf(d2v + pq, 1e-10f);
    float r0 = 1.0f / d0, r1 = 1.0f / d1, r2 = 1.0f / d2v;
    float inv = 1.0f / (r0 + r1 + r2);
    size_t base = ((size_t)b * N2 + n) * 3;
    g_idx[base]   = i0; g_idx[base+1] = i1; g_idx[base+2] = i2;
    g_wgt[base]   = r0*inv; g_wgt[base+1] = r1*inv; g_wgt[base+2] = r2*inv;
}

// ---------------- 2) build packed X1 image ([interp ; feat2]) ---------------
__global__ void buildX1_kernel(const float* __restrict__ feat1,
                               const float* __restrict__ feat2)
{
    const int b = blockIdx.y;
    const int n = blockIdx.x * blockDim.x + threadIdx.x;
    size_t base3 = ((size_t)b * N2 + n) * 3;
    const int   i0 = g_idx[base3], i1 = g_idx[base3+1], i2 = g_idx[base3+2];
    const float w0 = g_wgt[base3], w1 = g_wgt[base3+1], w2 = g_wgt[base3+2];
    const float* f1 = feat1 + (size_t)b * C1 * N1;
    const float* f2 = feat2 + (size_t)b * C2 * N2 + n;
    const int nl = n & 63;
    const uint32_t flip = (uint32_t)(nl & 2) << 4;   // 32 if n&2 else 0
    unsigned char* tb = g_Xim1 + ((size_t)b * NCH1 * N2 + (n & ~63)) * 64;

    #pragma unroll 1
    for (int c = 0; c < NCH1; ++c) {
        uint32_t arr[16];
        #pragma unroll
        for (int j = 0; j < 8; ++j) {
            const int k0 = c*16 + 2*j;
            float v0, v1;
            if (k0 < C1) {
                const float* r0 = f1 + (size_t)k0 * N1;
                const float* r1 = r0 + N1;
                v0 = w0*r0[i0] + w1*r0[i1] + w2*r0[i2];
                v1 = w0*r1[i0] + w1*r1[i1] + w2*r1[i2];
            } else {
                v0 = f2[(size_t)(k0 - C1) * N2];
                v1 = f2[(size_t)(k0 - C1 + 1) * N2];
            }
            const uint32_t h = pack_bf16(v0, v1);
            const uint32_t l = pack_bf16(v0 - bflo_f(h), v1 - bfhi_f(h));
            const int ph = (j < 4) ? 2*j : 2*(j-4) + 1;   // perm [0,4,1,5,2,6,3,7]
            arr[ph] = h; arr[ph + 8] = l;
        }
        unsigned char* tbase = tb + (size_t)c * N2 * 64;
        #pragma unroll
        for (int q = 0; q < 4; ++q) {
            const uint32_t sw = swz((uint32_t)nl*64 + ((uint32_t)(q*16) ^ flip));
            *(uint4*)(tbase + sw) = make_uint4(arr[4*q], arr[4*q+1], arr[4*q+2], arr[4*q+3]);
        }
    }
}

// ---------------- 5b) build packed X2 image (relu(bn(y1))) ------------------
__global__ void buildX2_kernel()
{
    const int b = blockIdx.y;
    const int n = blockIdx.x * blockDim.x + threadIdx.x;
    const float* yb = g_Y1 + (size_t)b * MOUT * N2 + n;
    const int nl = n & 63;
    const uint32_t flip = (uint32_t)(nl & 2) << 4;
    unsigned char* tb = g_Xim2 + ((size_t)b * NCH2 * N2 + (n & ~63)) * 64;

    #pragma unroll 1
    for (int c = 0; c < NCH2; ++c) {
        uint32_t arr[16];
        #pragma unroll
        for (int j = 0; j < 8; ++j) {
            const int k0 = c*16 + 2*j;
            float v0 = yb[(size_t)k0 * N2];
            float v1 = yb[(size_t)(k0+1) * N2];
            v0 = fmaxf(fmaf(v0, g_scale1[k0],   g_shift1[k0]),   0.0f);
            v1 = fmaxf(fmaf(v1, g_scale1[k0+1], g_shift1[k0+1]), 0.0f);
            const uint32_t h = pack_bf16(v0, v1);
            const uint32_t l = pack_bf16(v0 - bflo_f(h), v1 - bfhi_f(h));
            const int ph = (j < 4) ? 2*j : 2*(j-4) + 1;
            arr[ph] = h; arr[ph + 8] = l;
        }
        unsigned char* tbase = tb + (size_t)c * N2 * 64;
        #pragma unroll
        for (int q = 0; q < 4; ++q) {
            const uint32_t sw = swz((uint32_t)nl*64 + ((uint32_t)(q*16) ^ flip));
            *(uint4*)(tbase + sw) = make_uint4(arr[4*q], arr[4*q+1], arr[4*q+2], arr[4*q+3]);
        }
    }
}

// ---------------- prep: W -> bf16 hi/lo chunk-major smem images -------------
__global__ void prep_wimg_kernel(const float* __restrict__ W1,
                                 const float* __restrict__ W2)
{
    const int idx = blockIdx.x * blockDim.x + threadIdx.x;  // one row (c,m)
    if (idx < NCH1*256) {
        const int c = idx / 256, m = idx % 256;
        unsigned short* row = g_W1img + (size_t)idx * 40;
        #pragma unroll
        for (int k = 0; k < 16; ++k) {
            float v = W1[(size_t)m * CIN + c*16 + k];
            __nv_bfloat16 h = __float2bfloat16(v);
            __nv_bfloat16 l = __float2bfloat16(v - __bfloat162float(h));
            row[k]      = *reinterpret_cast<unsigned short*>(&h);
            row[16 + k] = *reinterpret_cast<unsigned short*>(&l);
        }
        #pragma unroll
        for (int k = 32; k < 40; ++k) row[k] = 0;
    }
    if (idx < NCH2*256) {
        const int c = idx / 256, m = idx % 256;
        unsigned short* row = g_W2img + (size_t)idx * 40;
        #pragma unroll
        for (int k = 0; k < 16; ++k) {
            float v = W2[(size_t)m * MOUT + c*16 + k];
            __nv_bfloat16 h = __float2bfloat16(v);
            __nv_bfloat16 l = __float2bfloat16(v - __bfloat162float(h));
            row[k]      = *reinterpret_cast<unsigned short*>(&h);
            row[16 + k] = *reinterpret_cast<unsigned short*>(&l);
        }
        #pragma unroll
        for (int k = 32; k < 40; ++k) row[k] = 0;
    }
}

// ---------------- mma / ldmatrix / async wrappers ---------------------------
__device__ __forceinline__ void mma_bf16(float* d, const uint32_t* a, const uint32_t* b)
{
    asm volatile(
        "mma.sync.aligned.m16n8k16.row.col.f32.bf16.bf16.f32 "
        "{%0,%1,%2,%3}, {%4,%5,%6,%7}, {%8,%9}, {%0,%1,%2,%3};\n"
        : "+f"(d[0]), "+f"(d[1]), "+f"(d[2]), "+f"(d[3])
        : "r"(a[0]), "r"(a[1]), "r"(a[2]), "r"(a[3]),
          "r"(b[0]), "r"(b[1]));
}
__device__ __forceinline__ void ldsm_x4(uint32_t* r, uint32_t saddr)
{
    asm volatile(
        "ldmatrix.sync.aligned.m8n8.x4.shared.b16 {%0,%1,%2,%3}, [%4];\n"
        : "=r"(r[0]), "=r"(r[1]), "=r"(r[2]), "=r"(r[3])
        : "r"(saddr));
}
__device__ __forceinline__ void lds64(uint32_t& a, uint32_t& b, uint32_t addr)
{
    asm volatile("ld.shared.v2.u32 {%0,%1}, [%2];" : "=r"(a), "=r"(b) : "r"(addr));
}
__device__ __forceinline__ void bulk_g2s(uint32_t dst, const void* src,
                                         uint32_t bytes, uint32_t mbar)
{
    asm volatile(
        "cp.async.bulk.shared::cluster.global.mbarrier::complete_tx::bytes "
        "[%0], [%1], %2, [%3];"
        :: "r"(dst), "l"(src), "r"(bytes), "r"(mbar) : "memory");
}
__device__ __forceinline__ void mbar_init(uint32_t mbar, uint32_t cnt)
{
    asm volatile("mbarrier.init.shared.b64 [%0], %1;" :: "r"(mbar), "r"(cnt) : "memory");
}
__device__ __forceinline__ void mbar_expect_tx(uint32_t mbar, uint32_t bytes)
{
    asm volatile("mbarrier.arrive.expect_tx.shared.b64 _, [%0], %1;"
                 :: "r"(mbar), "r"(bytes) : "memory");
}
__device__ __forceinline__ void mbar_wait(uint32_t mbar, uint32_t parity)
{
    asm volatile(
        "{\n\t.reg .pred P;\n\t"
        "W_%=:\n\t"
        "mbarrier.try_wait.parity.acquire.cta.shared::cta.b64 P, [%0], %1, 0x989680;\n\t"
        "@P bra D_%=;\n\t"
        "bra W_%=;\n\t"
        "D_%=:\n\t}"
        :: "r"(mbar), "r"(parity) : "memory");
}

// ---------------- 3/5) tensor-core GEMM: all-bulk loads, 3x bf16 k16 --------
// out[b,m,n2] = sum_k W[m,k]*X[k,(b,n2)] + bias[m]
// Wimg: bf16 hi/lo row images; Ximg: swizzled+flipped 64B-per-(chunk,n) recs.
// Emits per-block per-channel {sum,sumsq} into bpart (fused BN stats).
template<int K>
__global__ void __launch_bounds__(512, 2)
gemm_tc_kernel(const unsigned short* __restrict__ Wimg,
               const float* __restrict__ bias,
               const unsigned char* __restrict__ Ximg,
               float* __restrict__ out, float2* __restrict__ bpart)
{
    constexpr int NCH = K / 16;
    extern __shared__ char sm[];
    const uint32_t smb = (uint32_t)__cvta_generic_to_shared(sm);
    const uint32_t wsm = smb + WOFF;
    const uint32_t xsm = smb + XOFF;
    const uint32_t mb0 = smb + MBOFF;   // 3 mbarriers, 8B apart

    const int tid   = threadIdx.x;
    const int lane  = tid & 31;
    const int wid   = tid >> 5;         // 0..15
    const int g     = lane >> 2;
    const int tig   = lane & 3;
    const int mwarp = wid >> 1;         // 0..7 -> m base mwarp*32
    const int nwarp = wid & 1;          // 0..1 -> n base nwarp*32

    const int nglob = blockIdx.x * BNCOL;
    const int b     = nglob >> 13;
    const int n2    = nglob & (N2 - 1);

    const unsigned char* Xb = Ximg + ((size_t)b * NCH * N2 + n2) * 64;

    if (tid == 0) {
        mbar_init(mb0,      1);
        mbar_init(mb0 + 8,  1);
        mbar_init(mb0 + 16, 1);
    }
    __syncthreads();

    float acc[2][4][4];
    #pragma unroll
    for (int mt = 0; mt < 2; ++mt)
        #pragma unroll
        for (int nt = 0; nt < 4; ++nt)
            #pragma unroll
            for (int r = 0; r < 4; ++r) acc[mt][nt][r] = 0.0f;

    // ldmatrix lane address within a W stage (row stride 80B)
    const int rowoff  = ((lane >> 3) & 1) * 8 + (lane & 7);
    const int wordoff = (lane >> 4) * 4;
    const uint32_t aOff = ((((mwarp*32 + rowoff) * 20) + wordoff) << 2);

    // X smem offsets — swizzle applied to LOGICAL addresses, with per-column
    // hi/lo half flip (n&2) so each 16-lane LDS.64 phase is bank-conflict-free
    uint32_t xhoff[4], xloff[4];
    #pragma unroll
    for (int nt = 0; nt < 4; ++nt) {
        const uint32_t nn   = (uint32_t)(nwarp*32 + nt*8 + g);
        const uint32_t flip = (nn & 2) << 4;             // 32 if n&2 else 0
        const uint32_t base = nn * 64 + 8*tig;
        xhoff[nt] = swz(base + flip);
        xloff[nt] = swz(base + (flip ^ 32));
    }

    auto load_stage = [&](int c, int stg) {        // tid==0 only
        mbar_expect_tx(mb0 + stg * 8, W_STAGE + X_STAGE);
        bulk_g2s(wsm + stg * W_STAGE, Wimg + (size_t)c * (256*40),
                 W_STAGE, mb0 + stg * 8);
        bulk_g2s(xsm + stg * X_STAGE, Xb + (size_t)c * N2 * 64,
                 X_STAGE, mb0 + stg * 8);
    };

    if (tid == 0) { load_stage(0, 0); load_stage(1, 1); }

    int s = 0, ph = 0;
    for (int i = 0; i < NCH; ++i) {
        mbar_wait(mb0 + s * 8, (uint32_t)ph);
        __syncthreads();                           // data visible; old buffer free
        if (tid == 0 && i + 2 < NCH) load_stage(i + 2, (s + 2) % PSTAGES);

        const uint32_t aBase = wsm + s * W_STAGE + aOff;
        const uint32_t xb = xsm + s * X_STAGE;

        uint32_t bh[4][2], bl[4][2];
        #pragma unroll
        for (int nt = 0; nt < 4; ++nt) {
            lds64(bh[nt][0], bh[nt][1], xb + xhoff[nt]);
            lds64(bl[nt][0], bl[nt][1], xb + xloff[nt]);
        }
        #pragma unroll
        for (int mt = 0; mt < 2; ++mt) {
            uint32_t ah[4], al[4];
            ldsm_x4(ah, aBase + mt * 1280);        // hi (bytes 0..31 of row)
            ldsm_x4(al, aBase + mt * 1280 + 32);   // lo (bytes 32..63)
            #pragma unroll
            for (int nt = 0; nt < 4; ++nt) {
                mma_bf16(acc[mt][nt], ah, bh[nt]);   // hi*hi
                mma_bf16(acc[mt][nt], ah, bl[nt]);   // hi*lo
                mma_bf16(acc[mt][nt], al, bh[nt]);   // lo*hi
            }
        }
        __syncthreads();
        if (++s == PSTAGES) { s = 0; ph ^= 1; }
    }

    // ---- epilogue: bias add, store, fused per-channel stats ----
    float* part = (float*)sm;   // reuse W stage 0: [nwarp][256][{s,ss}]
    float* ob = out + (size_t)b * MOUT * N2 + n2;
    #pragma unroll
    for (int mt = 0; mt < 2; ++mt) {
        #pragma unroll
        for (int h = 0; h < 2; ++h) {
            const int m  = mwarp * 32 + mt * 16 + h * 8 + g;
            const float bv = bias[m];
            float s2 = 0.0f, ss = 0.0f;
            #pragma unroll
            for (int nt = 0; nt < 4; ++nt) {
                const float v0 = acc[mt][nt][h*2+0] + bv;
                const float v1 = acc[mt][nt][h*2+1] + bv;
                const int n = nwarp * 32 + nt * 8 + 2 * tig;
                *(float2*)(ob + (size_t)m * N2 + n) = make_float2(v0, v1);
                s2 += v0 + v1;
                ss += v0*v0 + v1*v1;
            }
            s2 += __shfl_xor_sync(0xffffffffu, s2, 1);
            s2 += __shfl_xor_sync(0xffffffffu, s2, 2);
            ss += __shfl_xor_sync(0xffffffffu, ss, 1);
            ss += __shfl_xor_sync(0xffffffffu, ss, 2);
            if (tig == 0) {
                part[(nwarp * 256 + m) * 2 + 0] = s2;
                part[(nwarp * 256 + m) * 2 + 1] = ss;
            }
        }
    }
    __syncthreads();
    if (tid < 256) {
        float2 r;
        r.x = part[tid * 2]     + part[(256 + tid) * 2];
        r.y = part[tid * 2 + 1] + part[(256 + tid) * 2 + 1];
        bpart[(size_t)blockIdx.x * MOUT + tid] = r;
    }
}

// ---------------- 4/6) stage-2 stats reduce ---------------------------------
__global__ void stats2_kernel(const float* __restrict__ gamma,
                              const float* __restrict__ beta,
                              float* __restrict__ scale,
                              float* __restrict__ shift)
{
    const int c = blockIdx.x;
    double s = 0.0, ss = 0.0;
    for (int j = threadIdx.x; j < NBLK; j += 256) {
        const float2 p = g_bpart[(size_t)j * MOUT + c];
        s  += (double)p.x;
        ss += (double)p.y;
    }
    __shared__ double rs[256], rss[256];
    rs[threadIdx.x] = s; rss[threadIdx.x] = ss;
    __syncthreads();
    for (int o = 128; o > 0; o >>= 1) {
        if (threadIdx.x < o) {
            rs[threadIdx.x]  += rs[threadIdx.x + o];
            rss[threadIdx.x] += rss[threadIdx.x + o];
        }
        __syncthreads();
    }
    if (threadIdx.x == 0) {
        const double mean = rs[0] / (double)NTOT;
        const double var  = rss[0] / (double)NTOT - mean * mean;
        const float istd  = (float)(1.0 / sqrt(var + 1e-3));
        const float sc    = gamma[c] * istd;
        scale[c] = sc;
        shift[c] = beta[c] - (float)mean * sc;
    }
}

// ---------------- 7) in-place BN+ReLU of layer-2 output ---------------------
__global__ void finalize_kernel(float* __restrict__ out)
{
    const size_t i4 = (size_t)blockIdx.x * blockDim.x + threadIdx.x;
    const int c = (int)((i4 >> 11) & 255);
    float4* p = (float4*)out + i4;
    float4 v = *p;
    const float sc = g_scale2[c], sh = g_shift2[c];
    v.x = fmaxf(fmaf(v.x, sc, sh), 0.0f);
    v.y = fmaxf(fmaf(v.y, sc, sh), 0.0f);
    v.z = fmaxf(fmaf(v.z, sc, sh), 0.0f);
    v.w = fmaxf(fmaf(v.w, sc, sh), 0.0f);
    *p = v;
}

// ---------------- launch ----------------------------------------------------
extern "C" void kernel_launch(void* const* d_in, const int* in_sizes, int n_in,
                              void* d_out, int out_size)
{
    const float* xyz2  = (const float*)d_in[0];
    const float* xyz1  = (const float*)d_in[1];
    const float* feat2 = (const float*)d_in[2];
    const float* feat1 = (const float*)d_in[3];
    const float* W1    = (const float*)d_in[4];
    const float* b1    = (const float*)d_in[5];
    const float* g1    = (const float*)d_in[6];
    const float* be1   = (const float*)d_in[7];
    const float* W2    = (const float*)d_in[8];
    const float* b2    = (const float*)d_in[9];
    const float* g2    = (const float*)d_in[10];
    const float* be2   = (const float*)d_in[11];
    float* out = (float*)d_out;

    float  *p_Y1, *p_s1, *p_sh1, *p_s2, *p_sh2;
    unsigned short *p_W1img, *p_W2img;
    unsigned char *p_X1, *p_X2;
    float2 *p_bpart;
    cudaGetSymbolAddress((void**)&p_Y1,     g_Y1);
    cudaGetSymbolAddress((void**)&p_s1,     g_scale1);
    cudaGetSymbolAddress((void**)&p_sh1,    g_shift1);
    cudaGetSymbolAddress((void**)&p_s2,     g_scale2);
    cudaGetSymbolAddress((void**)&p_sh2,    g_shift2);
    cudaGetSymbolAddress((void**)&p_bpart,  g_bpart);
    cudaGetSymbolAddress((void**)&p_W1img,  g_W1img);
    cudaGetSymbolAddress((void**)&p_W2img,  g_W2img);
    cudaGetSymbolAddress((void**)&p_X1,     g_Xim1);
    cudaGetSymbolAddress((void**)&p_X2,     g_Xim2);

    static int attr_done = 0;
    if (!attr_done) {
        cudaFuncSetAttribute(gemm_tc_kernel<CIN>,
                             cudaFuncAttributeMaxDynamicSharedMemorySize, SMEM_DYN);
        cudaFuncSetAttribute(gemm_tc_kernel<MOUT>,
                             cudaFuncAttributeMaxDynamicSharedMemorySize, SMEM_DYN);
        attr_done = 1;
    }

    knn_kernel<<<dim3(N2/256, BB), 256>>>(xyz2, xyz1);
    buildX1_kernel<<<dim3(N2/256, BB), 256>>>(feat1, feat2);
    prep_wimg_kernel<<<(NCH1*256 + 255)/256, 256>>>(W1, W2);

    // layer 1: y1 = W1 @ [interp; feat2] + b1 (raw) + fused stats partials
    gemm_tc_kernel<CIN><<<NBLK, 512, SMEM_DYN>>>(
        p_W1img, b1, p_X1, p_Y1, p_bpart);
    stats2_kernel<<<MOUT, 256>>>(g1, be1, p_s1, p_sh1);

    buildX2_kernel<<<dim3(N2/256, BB), 256>>>();

    // layer 2: y2 = W2 @ relu(bn(y1)) + b2 -> d_out (raw) + fused stats
    gemm_tc_kernel<MOUT><<<NBLK, 512, SMEM_DYN>>>(
        p_W2img, b2, p_X2, out, p_bpart);
    stats2_kernel<<<MOUT, 256>>>(g2, be2, p_s2, p_sh2);

    finalize_kernel<<<(NTOT * MOUT / 4) / 256, 256>>>(out);
}

// round 15
// speedup vs baseline: 1.0983x; 1.0983x over previous
#include <cuda_runtime.h>
#include <cuda_bf16.h>
#include <math.h>
#include <stdint.h>

#define BB    8
#define N1    2048
#define N2    8192
#define C1    256
#define C2    128
#define CIN   384
#define MOUT  256
#define NTOT  (BB*N2)      // 65536 columns
#define BNCOL 64           // GEMM block N
#define NBLK  (NTOT/BNCOL) // 1024 GEMM blocks
#define KP1   (CIN/2)      // 192 kpairs (GEMM1)
#define KP2   (MOUT/2)     // 128 kpairs (GEMM2)

// pipeline geometry
#define PSTAGES   3
#define XROW      72                           // X row stride (u32)
#define W_STAGE   (256*20*4)                   // 20480 B (one bulk copy)
#define X_STAGE   (16*XROW*4)                  // 4608 B (8 hi rows + 8 lo rows)
#define WOFF      0
#define XOFF      (PSTAGES*W_STAGE)            // 61440
#define MBOFF     (XOFF + PSTAGES*X_STAGE)     // 75264 (3 mbarriers)
#define SMEM_DYN  (MBOFF + 64)

#define WCH1 (CIN/16)   // 24 W chunks for GEMM1
#define WCH2 (MOUT/16)  // 16 W chunks for GEMM2

// ---------------- scratch (static __device__; no allocation) ----------------
__device__ int    g_idx[BB*N2*3];
__device__ float  g_wgt[BB*N2*3];
__device__ float  g_Y1[(size_t)BB*MOUT*N2];     // 67 MB raw layer-1 out
__device__ float  g_scale1[MOUT], g_shift1[MOUT];
__device__ float  g_scale2[MOUT], g_shift2[MOUT];
__device__ float2 g_bpart[(size_t)NBLK*MOUT];   // per-block {sum,sumsq}
// packed X planes: u32 = (bf16(k_odd)<<16)|bf16(k_even), [b][kpair][n]
__device__ uint32_t g_X1h[(size_t)BB*KP1*N2];   // 50 MB
__device__ uint32_t g_X1l[(size_t)BB*KP1*N2];
__device__ uint32_t g_X2h[(size_t)BB*KP2*N2];   // 34 MB
__device__ uint32_t g_X2l[(size_t)BB*KP2*N2];
// pre-baked W smem images (bf16 hi/lo per 16-k chunk):
// row m = 40 uint16: [0..15]=hi bf16, [16..31]=lo bf16, [32..39]=pad
__device__ __align__(128) unsigned short g_W1img[WCH1*256*40];
__device__ __align__(128) unsigned short g_W2img[WCH2*256*40];

__device__ __forceinline__ uint32_t pack_bf16(float lo, float hi)
{
    uint32_t r;
    asm volatile("cvt.rn.bf16x2.f32 %0, %1, %2;" : "=r"(r) : "f"(hi), "f"(lo));
    return r;
}
__device__ __forceinline__ float bflo_f(uint32_t p) { return __uint_as_float(p << 16); }
__device__ __forceinline__ float bfhi_f(uint32_t p) { return __uint_as_float(p & 0xFFFF0000u); }

// ---------------- 1) three_nn (3-FFMA distance) ------------------------------
__global__ void knn_kernel(const float* __restrict__ xyz2,
                           const float* __restrict__ xyz1)
{
    __shared__ float sx[N1], sy[N1], sz[N1], sq[N1];
    const int b = blockIdx.y;
    const float* p1 = xyz1 + (size_t)b * 3 * N1;
    for (int t = threadIdx.x; t < N1; t += blockDim.x) {
        const float x = p1[t], y = p1[N1 + t], z = p1[2*N1 + t];
        sx[t] = -2.0f * x; sy[t] = -2.0f * y; sz[t] = -2.0f * z;
        sq[t] = x*x + y*y + z*z;
    }
    __syncthreads();

    const int n = blockIdx.x * blockDim.x + threadIdx.x;
    const float* p2 = xyz2 + (size_t)b * 3 * N2;
    const float px = p2[n], py = p2[N2 + n], pz = p2[2*N2 + n];
    const float pq = px*px + py*py + pz*pz;

    float d0 = 3.4e38f, d1 = 3.4e38f, d2v = 3.4e38f;
    int   i0 = 0, i1 = 0, i2 = 0;
    #pragma unroll 4
    for (int j = 0; j < N1; ++j) {
        // d' = |q|^2 - 2 p.q  (true d = d' + |p|^2; constant shift per thread)
        const float d = fmaf(px, sx[j], fmaf(py, sy[j], fmaf(pz, sz[j], sq[j])));
        if (d < d2v) {
            if (d < d1) {
                d2v = d1; i2 = i1;
                if (d < d0) { d1 = d0; i1 = i0; d0 = d; i0 = j; }
                else        { d1 = d;  i1 = j; }
            } else { d2v = d; i2 = j; }
        }
    }
    d0  = fmaxf(d0  + pq, 1e-10f);
    d1  = fmaxf(d1  + pq, 1e-10f);
    d2v = fmaxf(d2v + pq, 1e-10f);
    float r0 = 1.0f / d0, r1 = 1.0f / d1, r2 = 1.0f / d2v;
    float inv = 1.0f / (r0 + r1 + r2);
    size_t base = ((size_t)b * N2 + n) * 3;
    g_idx[base]   = i0; g_idx[base+1] = i1; g_idx[base+2] = i2;
    g_wgt[base]   = r0*inv; g_wgt[base+1] = r1*inv; g_wgt[base+2] = r2*inv;
}

// ---------------- 2) build all packed X1 planes ([interp ; feat2]) ----------
__global__ void buildX1_kernel(const float* __restrict__ feat1,
                               const float* __restrict__ feat2)
{
    const int b = blockIdx.y;
    const int n = blockIdx.x * blockDim.x + threadIdx.x;
    size_t base = ((size_t)b * N2 + n) * 3;
    const int   i0 = g_idx[base], i1 = g_idx[base+1], i2 = g_idx[base+2];
    const float w0 = g_wgt[base], w1 = g_wgt[base+1], w2 = g_wgt[base+2];
    const float* f1 = feat1 + (size_t)b * C1 * N1;
    const float* f2 = feat2 + (size_t)b * C2 * N2 + n;
    uint32_t* Xh = g_X1h + (size_t)b * KP1 * N2 + n;
    uint32_t* Xl = g_X1l + (size_t)b * KP1 * N2 + n;
    #pragma unroll 2
    for (int c2 = 0; c2 < C1/2; ++c2) {
        const float* r0 = f1 + (2*c2) * N1;
        const float* r1 = r0 + N1;
        const float v0 = w0 * r0[i0] + w1 * r0[i1] + w2 * r0[i2];
        const float v1 = w0 * r1[i0] + w1 * r1[i1] + w2 * r1[i2];
        const uint32_t h = pack_bf16(v0, v1);
        Xh[(size_t)c2 * N2] = h;
        Xl[(size_t)c2 * N2] = pack_bf16(v0 - bflo_f(h), v1 - bfhi_f(h));
    }
    #pragma unroll 2
    for (int j2 = 0; j2 < C2/2; ++j2) {
        const float v0 = f2[(size_t)(2*j2)     * N2];
        const float v1 = f2[(size_t)(2*j2 + 1) * N2];
        const uint32_t h = pack_bf16(v0, v1);
        Xh[(size_t)(C1/2 + j2) * N2] = h;
        Xl[(size_t)(C1/2 + j2) * N2] = pack_bf16(v0 - bflo_f(h), v1 - bfhi_f(h));
    }
}

// ---------------- 5b) relu(bn(y1)) -> packed X2 planes ----------------------
__global__ void convY_kernel()
{
    const int b  = blockIdx.z;
    const int c2 = blockIdx.y;                   // 0..127
    const int n  = blockIdx.x * blockDim.x + threadIdx.x;
    const int k0 = 2*c2, k1 = 2*c2 + 1;
    float v0 = g_Y1[((size_t)b * MOUT + k0) * N2 + n];
    float v1 = g_Y1[((size_t)b * MOUT + k1) * N2 + n];
    v0 = fmaxf(fmaf(v0, g_scale1[k0], g_shift1[k0]), 0.0f);
    v1 = fmaxf(fmaf(v1, g_scale1[k1], g_shift1[k1]), 0.0f);
    const uint32_t h = pack_bf16(v0, v1);
    const size_t o = ((size_t)b * KP2 + c2) * N2 + n;
    g_X2h[o] = h;
    g_X2l[o] = pack_bf16(v0 - bflo_f(h), v1 - bfhi_f(h));
}

// ---------------- prep: W -> bf16 hi/lo chunk-major smem images -------------
__global__ void prep_wimg_kernel(const float* __restrict__ W1,
                                 const float* __restrict__ W2)
{
    const int idx = blockIdx.x * blockDim.x + threadIdx.x;  // one row (c,m)
    if (idx < WCH1*256) {
        const int c = idx / 256, m = idx % 256;
        unsigned short* row = g_W1img + (size_t)idx * 40;
        #pragma unroll
        for (int k = 0; k < 16; ++k) {
            float v = W1[(size_t)m * CIN + c*16 + k];
            __nv_bfloat16 h = __float2bfloat16(v);
            __nv_bfloat16 l = __float2bfloat16(v - __bfloat162float(h));
            row[k]      = *reinterpret_cast<unsigned short*>(&h);
            row[16 + k] = *reinterpret_cast<unsigned short*>(&l);
        }
        #pragma unroll
        for (int k = 32; k < 40; ++k) row[k] = 0;
    }
    if (idx < WCH2*256) {
        const int c = idx / 256, m = idx % 256;
        unsigned short* row = g_W2img + (size_t)idx * 40;
        #pragma unroll
        for (int k = 0; k < 16; ++k) {
            float v = W2[(size_t)m * MOUT + c*16 + k];
            __nv_bfloat16 h = __float2bfloat16(v);
            __nv_bfloat16 l = __float2bfloat16(v - __bfloat162float(h));
            row[k]      = *reinterpret_cast<unsigned short*>(&h);
            row[16 + k] = *reinterpret_cast<unsigned short*>(&l);
        }
        #pragma unroll
        for (int k = 32; k < 40; ++k) row[k] = 0;
    }
}

// ---------------- mma / ldmatrix / async wrappers ---------------------------
__device__ __forceinline__ void mma_bf16(float* d, const uint32_t* a, const uint32_t* b)
{
    asm volatile(
        "mma.sync.aligned.m16n8k16.row.col.f32.bf16.bf16.f32 "
        "{%0,%1,%2,%3}, {%4,%5,%6,%7}, {%8,%9}, {%0,%1,%2,%3};\n"
        : "+f"(d[0]), "+f"(d[1]), "+f"(d[2]), "+f"(d[3])
        : "r"(a[0]), "r"(a[1]), "r"(a[2]), "r"(a[3]),
          "r"(b[0]), "r"(b[1]));
}
__device__ __forceinline__ void ldsm_x4(uint32_t* r, uint32_t saddr)
{
    asm volatile(
        "ldmatrix.sync.aligned.m8n8.x4.shared.b16 {%0,%1,%2,%3}, [%4];\n"
        : "=r"(r[0]), "=r"(r[1]), "=r"(r[2]), "=r"(r[3])
        : "r"(saddr));
}
__device__ __forceinline__ void cp_async16(uint32_t dst, const void* src)
{
    asm volatile("cp.async.cg.shared.global [%0], [%1], 16;\n"
                 :: "r"(dst), "l"(src));
}
__device__ __forceinline__ void cp_commit()
{
    asm volatile("cp.async.commit_group;\n");
}
template<int N>
__device__ __forceinline__ void cp_wait()
{
    asm volatile("cp.async.wait_group %0;\n" :: "n"(N));
}
__device__ __forceinline__ void bulk_g2s(uint32_t dst, const void* src,
                                         uint32_t bytes, uint32_t mbar)
{
    asm volatile(
        "cp.async.bulk.shared::cluster.global.mbarrier::complete_tx::bytes "
        "[%0], [%1], %2, [%3];"
        :: "r"(dst), "l"(src), "r"(bytes), "r"(mbar) : "memory");
}
__device__ __forceinline__ void mbar_init(uint32_t mbar, uint32_t cnt)
{
    asm volatile("mbarrier.init.shared.b64 [%0], %1;" :: "r"(mbar), "r"(cnt) : "memory");
}
__device__ __forceinline__ void mbar_expect_tx(uint32_t mbar, uint32_t bytes)
{
    asm volatile("mbarrier.arrive.expect_tx.shared.b64 _, [%0], %1;"
                 :: "r"(mbar), "r"(bytes) : "memory");
}
__device__ __forceinline__ void mbar_wait(uint32_t mbar, uint32_t parity)
{
    asm volatile(
        "{\n\t.reg .pred P;\n\t"
        "W_%=:\n\t"
        "mbarrier.try_wait.parity.acquire.cta.shared::cta.b64 P, [%0], %1, 0x989680;\n\t"
        "@P bra D_%=;\n\t"
        "bra W_%=;\n\t"
        "D_%=:\n\t}"
        :: "r"(mbar), "r"(parity) : "memory");
}

// ---------------- 3/5) tensor-core GEMM, 3x bf16 k16, pre-packed X ----------
// out[b,m,n2] = sum_k W[m,k]*X[k,(b,n2)] + bias[m]
// Wimg = bf16 hi/lo smem images (bulk-loaded); Xh/Xl = packed u32 pair-planes.
// Emits per-block per-channel {sum,sumsq} into bpart (fused BN stats).
template<int K>
__global__ void __launch_bounds__(512, 2)
gemm_tc_kernel(const unsigned short* __restrict__ Wimg,
               const float* __restrict__ bias,
               const uint32_t* __restrict__ Xh, const uint32_t* __restrict__ Xl,
               float* __restrict__ out, float2* __restrict__ bpart)
{
    constexpr int KP = K / 2;
    extern __shared__ char sm[];
    const uint32_t smb = (uint32_t)__cvta_generic_to_shared(sm);
    const uint32_t wsm = smb + WOFF;
    const uint32_t xsm = smb + XOFF;
    const uint32_t mb0 = smb + MBOFF;   // 3 mbarriers, 8B apart

    const int tid   = threadIdx.x;
    const int lane  = tid & 31;
    const int wid   = tid >> 5;         // 0..15
    const int g     = lane >> 2;
    const int tig   = lane & 3;
    const int mwarp = wid >> 1;         // 0..7 -> m base mwarp*32
    const int nwarp = wid & 1;          // 0..1 -> n base nwarp*32

    const int nglob = blockIdx.x * BNCOL;
    const int b     = nglob >> 13;
    const int n2    = nglob & (N2 - 1);

    const uint32_t* Xhb = Xh + (size_t)b * KP * N2 + n2;
    const uint32_t* Xlb = Xl + (size_t)b * KP * N2 + n2;

    if (tid == 0) {
        mbar_init(mb0,      1);
        mbar_init(mb0 + 8,  1);
        mbar_init(mb0 + 16, 1);
    }
    __syncthreads();

    float acc[2][4][4];
    #pragma unroll
    for (int mt = 0; mt < 2; ++mt)
        #pragma unroll
        for (int nt = 0; nt < 4; ++nt)
            #pragma unroll
            for (int r = 0; r < 4; ++r) acc[mt][nt][r] = 0.0f;

    // ldmatrix lane address within a W stage (row stride 80B)
    const int rowoff  = ((lane >> 3) & 1) * 8 + (lane & 7);
    const int wordoff = (lane >> 4) * 4;
    const uint32_t aOff = ((((mwarp*32 + rowoff) * 20) + wordoff) << 2);

    auto load_W = [&](int chunk, int stg) {        // tid==0 only
        mbar_expect_tx(mb0 + stg * 8, W_STAGE);
        bulk_g2s(wsm + stg * W_STAGE, Wimg + (size_t)chunk * (256*40),
                 W_STAGE, mb0 + stg * 8);
    };
    // X tile per stage: 8 kpair rows x 64 u32, hi rows 0..7, lo rows 8..15
    auto load_X = [&](int kp0, int stg) {          // tid<256
        if (tid < 256) {
            const int plane = tid >> 7;            // 0=hi, 1=lo
            const int t2  = tid & 127;
            const int xkr = t2 >> 4;               // 0..7
            const int xn4 = (t2 & 15) * 4;         // u32 quad
            const uint32_t* src = (plane ? Xlb : Xhb) + (size_t)(kp0 + xkr) * N2 + xn4;
            cp_async16(xsm + stg * X_STAGE
                           + (((plane*8 + xkr) * XROW + xn4) << 2), src);
        }
    };

    constexpr int NITER = K / 16;
    #pragma unroll
    for (int p = 0; p < PSTAGES - 1; ++p) {
        if (tid == 0) load_W(p, p);
        load_X(p * 8, p);
        cp_commit();
    }

    int s = 0, ph = 0;
    for (int i = 0; i < NITER; ++i) {
        const int inext = i + PSTAGES - 1;
        const int sN = (s + PSTAGES - 1) % PSTAGES;
        if (inext < NITER) load_X(inext * 8, sN);
        cp_commit();
        cp_wait<PSTAGES - 2>();
        mbar_wait(mb0 + s * 8, (uint32_t)ph);
        __syncthreads();
        if (inext < NITER && tid == 0) load_W(inext, sN);

        const uint32_t aBase = wsm + s * W_STAGE + aOff;
        const uint32_t* Xs = (const uint32_t*)(sm + XOFF + s * X_STAGE);

        // b-fragments: direct packed loads, no conversion
        uint32_t bh[4][2], bl[4][2];
        #pragma unroll
        for (int nt = 0; nt < 4; ++nt) {
            const int nn = nwarp * 32 + nt * 8 + g;
            bh[nt][0] = Xs[tig * XROW + nn];
            bh[nt][1] = Xs[(tig + 4) * XROW + nn];
            bl[nt][0] = Xs[(8 + tig) * XROW + nn];
            bl[nt][1] = Xs[(8 + tig + 4) * XROW + nn];
        }

        #pragma unroll
        for (int mt = 0; mt < 2; ++mt) {
            uint32_t ah[4], al[4];
            ldsm_x4(ah, aBase + mt * 1280);        // hi (bytes 0..31 of row)
            ldsm_x4(al, aBase + mt * 1280 + 32);   // lo (bytes 32..63)
            #pragma unroll
            for (int nt = 0; nt < 4; ++nt) {
                mma_bf16(acc[mt][nt], ah, bh[nt]);   // hi*hi
                mma_bf16(acc[mt][nt], ah, bl[nt]);   // hi*lo
                mma_bf16(acc[mt][nt], al, bh[nt]);   // lo*hi
            }
        }
        __syncthreads();
        if (++s == PSTAGES) { s = 0; ph ^= 1; }
    }

    // ---- epilogue: bias add, store, fused per-channel stats ----
    float* part = (float*)sm;   // reuse W stage 0: [nwarp][256][{s,ss}]
    float* ob = out + (size_t)b * MOUT * N2 + n2;
    #pragma unroll
    for (int mt = 0; mt < 2; ++mt) {
        #pragma unroll
        for (int h = 0; h < 2; ++h) {
            const int m  = mwarp * 32 + mt * 16 + h * 8 + g;
            const float bv = bias[m];
            float s2 = 0.0f, ss = 0.0f;
            #pragma unroll
            for (int nt = 0; nt < 4; ++nt) {
                const float v0 = acc[mt][nt][h*2+0] + bv;
                const float v1 = acc[mt][nt][h*2+1] + bv;
                const int n = nwarp * 32 + nt * 8 + 2 * tig;
                *(float2*)(ob + (size_t)m * N2 + n) = make_float2(v0, v1);
                s2 += v0 + v1;
                ss += v0*v0 + v1*v1;
            }
            s2 += __shfl_xor_sync(0xffffffffu, s2, 1);
            s2 += __shfl_xor_sync(0xffffffffu, s2, 2);
            ss += __shfl_xor_sync(0xffffffffu, ss, 1);
            ss += __shfl_xor_sync(0xffffffffu, ss, 2);
            if (tig == 0) {
                part[(nwarp * 256 + m) * 2 + 0] = s2;
                part[(nwarp * 256 + m) * 2 + 1] = ss;
            }
        }
    }
    __syncthreads();
    if (tid < 256) {
        float2 r;
        r.x = part[tid * 2]     + part[(256 + tid) * 2];
        r.y = part[tid * 2 + 1] + part[(256 + tid) * 2 + 1];
        bpart[(size_t)blockIdx.x * MOUT + tid] = r;
    }
}

// ---------------- 4/6) stage-2 stats reduce ---------------------------------
__global__ void stats2_kernel(const float* __restrict__ gamma,
                              const float* __restrict__ beta,
                              float* __restrict__ scale,
                              float* __restrict__ shift)
{
    const int c = blockIdx.x;
    double s = 0.0, ss = 0.0;
    for (int j = threadIdx.x; j < NBLK; j += 256) {
        const float2 p = g_bpart[(size_t)j * MOUT + c];
        s  += (double)p.x;
        ss += (double)p.y;
    }
    __shared__ double rs[256], rss[256];
    rs[threadIdx.x] = s; rss[threadIdx.x] = ss;
    __syncthreads();
    for (int o = 128; o > 0; o >>= 1) {
        if (threadIdx.x < o) {
            rs[threadIdx.x]  += rs[threadIdx.x + o];
            rss[threadIdx.x] += rss[threadIdx.x + o];
        }
        __syncthreads();
    }
    if (threadIdx.x == 0) {
        const double mean = rs[0] / (double)NTOT;
        const double var  = rss[0] / (double)NTOT - mean * mean;
        const float istd  = (float)(1.0 / sqrt(var + 1e-3));
        const float sc    = gamma[c] * istd;
        scale[c] = sc;
        shift[c] = beta[c] - (float)mean * sc;
    }
}

// ---------------- 7) in-place BN+ReLU of layer-2 output ---------------------
__global__ void finalize_kernel(float* __restrict__ out)
{
    const size_t i4 = (size_t)blockIdx.x * blockDim.x + threadIdx.x;
    const int c = (int)((i4 >> 11) & 255);
    float4* p = (float4*)out + i4;
    float4 v = *p;
    const float sc = g_scale2[c], sh = g_shift2[c];
    v.x = fmaxf(fmaf(v.x, sc, sh), 0.0f);
    v.y = fmaxf(fmaf(v.y, sc, sh), 0.0f);
    v.z = fmaxf(fmaf(v.z, sc, sh), 0.0f);
    v.w = fmaxf(fmaf(v.w, sc, sh), 0.0f);
    *p = v;
}

// ---------------- launch ----------------------------------------------------
extern "C" void kernel_launch(void* const* d_in, const int* in_sizes, int n_in,
                              void* d_out, int out_size)
{
    const float* xyz2  = (const float*)d_in[0];
    const float* xyz1  = (const float*)d_in[1];
    const float* feat2 = (const float*)d_in[2];
    const float* feat1 = (const float*)d_in[3];
    const float* W1    = (const float*)d_in[4];
    const float* b1    = (const float*)d_in[5];
    const float* g1    = (const float*)d_in[6];
    const float* be1   = (const float*)d_in[7];
    const float* W2    = (const float*)d_in[8];
    const float* b2    = (const float*)d_in[9];
    const float* g2    = (const float*)d_in[10];
    const float* be2   = (const float*)d_in[11];
    float* out = (float*)d_out;

    float  *p_Y1, *p_s1, *p_sh1, *p_s2, *p_sh2;
    unsigned short *p_W1img, *p_W2img;
    uint32_t *p_X1h, *p_X1l, *p_X2h, *p_X2l;
    float2 *p_bpart;
    cudaGetSymbolAddress((void**)&p_Y1,     g_Y1);
    cudaGetSymbolAddress((void**)&p_s1,     g_scale1);
    cudaGetSymbolAddress((void**)&p_sh1,    g_shift1);
    cudaGetSymbolAddress((void**)&p_s2,     g_scale2);
    cudaGetSymbolAddress((void**)&p_sh2,    g_shift2);
    cudaGetSymbolAddress((void**)&p_bpart,  g_bpart);
    cudaGetSymbolAddress((void**)&p_W1img,  g_W1img);
    cudaGetSymbolAddress((void**)&p_W2img,  g_W2img);
    cudaGetSymbolAddress((void**)&p_X1h,    g_X1h);
    cudaGetSymbolAddress((void**)&p_X1l,    g_X1l);
    cudaGetSymbolAddress((void**)&p_X2h,    g_X2h);
    cudaGetSymbolAddress((void**)&p_X2l,    g_X2l);

    static int attr_done = 0;
    if (!attr_done) {
        cudaFuncSetAttribute(gemm_tc_kernel<CIN>,
                             cudaFuncAttributeMaxDynamicSharedMemorySize, SMEM_DYN);
        cudaFuncSetAttribute(gemm_tc_kernel<MOUT>,
                             cudaFuncAttributeMaxDynamicSharedMemorySize, SMEM_DYN);
        attr_done = 1;
    }

    knn_kernel<<<dim3(N2/256, BB), 256>>>(xyz2, xyz1);
    buildX1_kernel<<<dim3(N2/256, BB), 256>>>(feat1, feat2);
    prep_wimg_kernel<<<(WCH1*256 + 255)/256, 256>>>(W1, W2);

    // layer 1: y1 = W1 @ [interp; feat2] + b1 (raw) + fused stats partials
    gemm_tc_kernel<CIN><<<NBLK, 512, SMEM_DYN>>>(
        p_W1img, b1, p_X1h, p_X1l, p_Y1, p_bpart);
    stats2_kernel<<<MOUT, 256>>>(g1, be1, p_s1, p_sh1);

    convY_kernel<<<dim3(N2/256, MOUT/2, BB), 256>>>();

    // layer 2: y2 = W2 @ relu(bn(y1)) + b2 -> d_out (raw) + fused stats
    gemm_tc_kernel<MOUT><<<NBLK, 512, SMEM_DYN>>>(
        p_W2img, b2, p_X2h, p_X2l, out, p_bpart);
    stats2_kernel<<<MOUT, 256>>>(g2, be2, p_s2, p_sh2);

    finalize_kernel<<<(NTOT * MOUT / 4) / 256, 256>>>(out);
}

// round 16
// speedup vs baseline: 1.1001x; 1.0016x over previous
#include <cuda_runtime.h>
#include <cuda_bf16.h>
#include <math.h>
#include <stdint.h>

#define BB    8
#define N1    2048
#define N2    8192
#define C1    256
#define C2    128
#define CIN   384
#define MOUT  256
#define NTOT  (BB*N2)      // 65536 columns
#define BNCOL 64           // GEMM block N
#define NBLK  (NTOT/BNCOL) // 1024 GEMM blocks
#define KP1   (CIN/2)      // 192 kpairs (GEMM1)
#define KP2   (MOUT/2)     // 128 kpairs (GEMM2)

// pipeline geometry
#define PSTAGES   3
#define XROW      72                           // X row stride (u32)
#define W_STAGE   (256*20*4)                   // 20480 B (one bulk copy)
#define X_STAGE   (16*XROW*4)                  // 4608 B (8 hi rows + 8 lo rows)
#define WOFF      0
#define XOFF      (PSTAGES*W_STAGE)            // 61440
#define MBOFF     (XOFF + PSTAGES*X_STAGE)     // 75264 (3 mbarriers)
#define SMEM_DYN  (MBOFF + 64)

#define WCH1 (CIN/16)   // 24 W chunks for GEMM1
#define WCH2 (MOUT/16)  // 16 W chunks for GEMM2

// ---------------- scratch (static __device__; no allocation) ----------------
__device__ int    g_idx[BB*N2*3];
__device__ float  g_wgt[BB*N2*3];
__device__ float  g_Y1[(size_t)BB*MOUT*N2];     // 67 MB raw layer-1 out
__device__ float  g_scale1[MOUT], g_shift1[MOUT];
__device__ float  g_scale2[MOUT], g_shift2[MOUT];
__device__ float2 g_bpart[(size_t)NBLK*MOUT];   // per-block {sum,sumsq}
// packed X planes: u32 = (bf16(k_odd)<<16)|bf16(k_even), [b][kpair][n_perm]
// column permutation within 16-col groups: ns = (n&~15)|((n&7)<<1)|((n>>3)&1)
// so logical columns g and g+8 are adjacent -> b-fragments load via LDS.64
__device__ uint32_t g_X1h[(size_t)BB*KP1*N2];   // 50 MB
__device__ uint32_t g_X1l[(size_t)BB*KP1*N2];
__device__ uint32_t g_X2h[(size_t)BB*KP2*N2];   // 34 MB
__device__ uint32_t g_X2l[(size_t)BB*KP2*N2];
// pre-baked W smem images (bf16 hi/lo per 16-k chunk):
// row m = 40 uint16: [0..15]=hi bf16, [16..31]=lo bf16, [32..39]=pad
__device__ __align__(128) unsigned short g_W1img[WCH1*256*40];
__device__ __align__(128) unsigned short g_W2img[WCH2*256*40];

__device__ __forceinline__ uint32_t pack_bf16(float lo, float hi)
{
    uint32_t r;
    asm volatile("cvt.rn.bf16x2.f32 %0, %1, %2;" : "=r"(r) : "f"(hi), "f"(lo));
    return r;
}
__device__ __forceinline__ float bflo_f(uint32_t p) { return __uint_as_float(p << 16); }
__device__ __forceinline__ float bfhi_f(uint32_t p) { return __uint_as_float(p & 0xFFFF0000u); }
__device__ __forceinline__ int colperm(int n)
{
    return (n & ~15) | ((n & 7) << 1) | ((n >> 3) & 1);
}

// ---------------- 1) three_nn (3-FFMA distance) ------------------------------
__global__ void knn_kernel(const float* __restrict__ xyz2,
                           const float* __restrict__ xyz1)
{
    __shared__ float sx[N1], sy[N1], sz[N1], sq[N1];
    const int b = blockIdx.y;
    const float* p1 = xyz1 + (size_t)b * 3 * N1;
    for (int t = threadIdx.x; t < N1; t += blockDim.x) {
        const float x = p1[t], y = p1[N1 + t], z = p1[2*N1 + t];
        sx[t] = -2.0f * x; sy[t] = -2.0f * y; sz[t] = -2.0f * z;
        sq[t] = x*x + y*y + z*z;
    }
    __syncthreads();

    const int n = blockIdx.x * blockDim.x + threadIdx.x;
    const float* p2 = xyz2 + (size_t)b * 3 * N2;
    const float px = p2[n], py = p2[N2 + n], pz = p2[2*N2 + n];
    const float pq = px*px + py*py + pz*pz;

    float d0 = 3.4e38f, d1 = 3.4e38f, d2v = 3.4e38f;
    int   i0 = 0, i1 = 0, i2 = 0;
    #pragma unroll 4
    for (int j = 0; j < N1; ++j) {
        const float d = fmaf(px, sx[j], fmaf(py, sy[j], fmaf(pz, sz[j], sq[j])));
        if (d < d2v) {
            if (d < d1) {
                d2v = d1; i2 = i1;
                if (d < d0) { d1 = d0; i1 = i0; d0 = d; i0 = j; }
                else        { d1 = d;  i1 = j; }
            } else { d2v = d; i2 = j; }
        }
    }
    d0  = fmaxf(d0  + pq, 1e-10f);
    d1  = fmaxf(d1  + pq, 1e-10f);
    d2v = fmaxf(d2v + pq, 1e-10f);
    float r0 = 1.0f / d0, r1 = 1.0f / d1, r2 = 1.0f / d2v;
    float inv = 1.0f / (r0 + r1 + r2);
    size_t base = ((size_t)b * N2 + n) * 3;
    g_idx[base]   = i0; g_idx[base+1] = i1; g_idx[base+2] = i2;
    g_wgt[base]   = r0*inv; g_wgt[base+1] = r1*inv; g_wgt[base+2] = r2*inv;
}

// ---------------- 2) build all packed X1 planes ([interp ; feat2]) ----------
__global__ void buildX1_kernel(const float* __restrict__ feat1,
                               const float* __restrict__ feat2)
{
    const int b = blockIdx.y;
    const int n = blockIdx.x * blockDim.x + threadIdx.x;
    size_t base = ((size_t)b * N2 + n) * 3;
    const int   i0 = g_idx[base], i1 = g_idx[base+1], i2 = g_idx[base+2];
    const float w0 = g_wgt[base], w1 = g_wgt[base+1], w2 = g_wgt[base+2];
    const float* f1 = feat1 + (size_t)b * C1 * N1;
    const float* f2 = feat2 + (size_t)b * C2 * N2 + n;
    const int ns = colperm(n);                      // permuted store column
    uint32_t* Xh = g_X1h + (size_t)b * KP1 * N2 + ns;
    uint32_t* Xl = g_X1l + (size_t)b * KP1 * N2 + ns;
    #pragma unroll 2
    for (int c2 = 0; c2 < C1/2; ++c2) {
        const float* r0 = f1 + (2*c2) * N1;
        const float* r1 = r0 + N1;
        const float v0 = w0 * r0[i0] + w1 * r0[i1] + w2 * r0[i2];
        const float v1 = w0 * r1[i0] + w1 * r1[i1] + w2 * r1[i2];
        const uint32_t h = pack_bf16(v0, v1);
        Xh[(size_t)c2 * N2] = h;
        Xl[(size_t)c2 * N2] = pack_bf16(v0 - bflo_f(h), v1 - bfhi_f(h));
    }
    #pragma unroll 2
    for (int j2 = 0; j2 < C2/2; ++j2) {
        const float v0 = f2[(size_t)(2*j2)     * N2];
        const float v1 = f2[(size_t)(2*j2 + 1) * N2];
        const uint32_t h = pack_bf16(v0, v1);
        Xh[(size_t)(C1/2 + j2) * N2] = h;
        Xl[(size_t)(C1/2 + j2) * N2] = pack_bf16(v0 - bflo_f(h), v1 - bfhi_f(h));
    }
}

// ---------------- 5b) relu(bn(y1)) -> packed X2 planes ----------------------
__global__ void convY_kernel()
{
    const int b  = blockIdx.z;
    const int c2 = blockIdx.y;                   // 0..127
    const int n  = blockIdx.x * blockDim.x + threadIdx.x;
    const int k0 = 2*c2, k1 = 2*c2 + 1;
    float v0 = g_Y1[((size_t)b * MOUT + k0) * N2 + n];
    float v1 = g_Y1[((size_t)b * MOUT + k1) * N2 + n];
    v0 = fmaxf(fmaf(v0, g_scale1[k0], g_shift1[k0]), 0.0f);
    v1 = fmaxf(fmaf(v1, g_scale1[k1], g_shift1[k1]), 0.0f);
    const uint32_t h = pack_bf16(v0, v1);
    const size_t o = ((size_t)b * KP2 + c2) * N2 + colperm(n);
    g_X2h[o] = h;
    g_X2l[o] = pack_bf16(v0 - bflo_f(h), v1 - bfhi_f(h));
}

// ---------------- prep: W -> bf16 hi/lo chunk-major smem images -------------
__global__ void prep_wimg_kernel(const float* __restrict__ W1,
                                 const float* __restrict__ W2)
{
    const int idx = blockIdx.x * blockDim.x + threadIdx.x;  // one row (c,m)
    if (idx < WCH1*256) {
        const int c = idx / 256, m = idx % 256;
        unsigned short* row = g_W1img + (size_t)idx * 40;
        #pragma unroll
        for (int k = 0; k < 16; ++k) {
            float v = W1[(size_t)m * CIN + c*16 + k];
            __nv_bfloat16 h = __float2bfloat16(v);
            __nv_bfloat16 l = __float2bfloat16(v - __bfloat162float(h));
            row[k]      = *reinterpret_cast<unsigned short*>(&h);
            row[16 + k] = *reinterpret_cast<unsigned short*>(&l);
        }
        #pragma unroll
        for (int k = 32; k < 40; ++k) row[k] = 0;
    }
    if (idx < WCH2*256) {
        const int c = idx / 256, m = idx % 256;
        unsigned short* row = g_W2img + (size_t)idx * 40;
        #pragma unroll
        for (int k = 0; k < 16; ++k) {
            float v = W2[(size_t)m * MOUT + c*16 + k];
            __nv_bfloat16 h = __float2bfloat16(v);
            __nv_bfloat16 l = __float2bfloat16(v - __bfloat162float(h));
            row[k]      = *reinterpret_cast<unsigned short*>(&h);
            row[16 + k] = *reinterpret_cast<unsigned short*>(&l);
        }
        #pragma unroll
        for (int k = 32; k < 40; ++k) row[k] = 0;
    }
}

// ---------------- mma / ldmatrix / async wrappers ---------------------------
__device__ __forceinline__ void mma_bf16(float* d, const uint32_t* a, const uint32_t* b)
{
    asm volatile(
        "mma.sync.aligned.m16n8k16.row.col.f32.bf16.bf16.f32 "
        "{%0,%1,%2,%3}, {%4,%5,%6,%7}, {%8,%9}, {%0,%1,%2,%3};\n"
        : "+f"(d[0]), "+f"(d[1]), "+f"(d[2]), "+f"(d[3])
        : "r"(a[0]), "r"(a[1]), "r"(a[2]), "r"(a[3]),
          "r"(b[0]), "r"(b[1]));
}
__device__ __forceinline__ void ldsm_x4(uint32_t* r, uint32_t saddr)
{
    asm volatile(
        "ldmatrix.sync.aligned.m8n8.x4.shared.b16 {%0,%1,%2,%3}, [%4];\n"
        : "=r"(r[0]), "=r"(r[1]), "=r"(r[2]), "=r"(r[3])
        : "r"(saddr));
}
__device__ __forceinline__ void lds64(uint32_t& a, uint32_t& b, uint32_t addr)
{
    asm volatile("ld.shared.v2.u32 {%0,%1}, [%2];" : "=r"(a), "=r"(b) : "r"(addr));
}
__device__ __forceinline__ void cp_async16(uint32_t dst, const void* src)
{
    asm volatile("cp.async.cg.shared.global [%0], [%1], 16;\n"
                 :: "r"(dst), "l"(src));
}
__device__ __forceinline__ void cp_commit()
{
    asm volatile("cp.async.commit_group;\n");
}
template<int N>
__device__ __forceinline__ void cp_wait()
{
    asm volatile("cp.async.wait_group %0;\n" :: "n"(N));
}
__device__ __forceinline__ void bulk_g2s(uint32_t dst, const void* src,
                                         uint32_t bytes, uint32_t mbar)
{
    asm volatile(
        "cp.async.bulk.shared::cluster.global.mbarrier::complete_tx::bytes "
        "[%0], [%1], %2, [%3];"
        :: "r"(dst), "l"(src), "r"(bytes), "r"(mbar) : "memory");
}
__device__ __forceinline__ void mbar_init(uint32_t mbar, uint32_t cnt)
{
    asm volatile("mbarrier.init.shared.b64 [%0], %1;" :: "r"(mbar), "r"(cnt) : "memory");
}
__device__ __forceinline__ void mbar_expect_tx(uint32_t mbar, uint32_t bytes)
{
    asm volatile("mbarrier.arrive.expect_tx.shared.b64 _, [%0], %1;"
                 :: "r"(mbar), "r"(bytes) : "memory");
}
__device__ __forceinline__ void mbar_wait(uint32_t mbar, uint32_t parity)
{
    asm volatile(
        "{\n\t.reg .pred P;\n\t"
        "W_%=:\n\t"
        "mbarrier.try_wait.parity.acquire.cta.shared::cta.b64 P, [%0], %1, 0x989680;\n\t"
        "@P bra D_%=;\n\t"
        "bra W_%=;\n\t"
        "D_%=:\n\t}"
        :: "r"(mbar), "r"(parity) : "memory");
}

// ---------------- 3/5) tensor-core GEMM, 3x bf16 k16, pre-packed X ----------
// out[b,m,n2] = sum_k W[m,k]*X[k,(b,n2)] + bias[m]
// Wimg = bf16 hi/lo smem images (bulk-loaded); Xh/Xl = packed u32 pair-planes
// with interleaved columns -> b-fragment pairs load via LDS.64.
// Emits per-block per-channel {sum,sumsq} into bpart (fused BN stats).
template<int K>
__global__ void __launch_bounds__(512, 2)
gemm_tc_kernel(const unsigned short* __restrict__ Wimg,
               const float* __restrict__ bias,
               const uint32_t* __restrict__ Xh, const uint32_t* __restrict__ Xl,
               float* __restrict__ out, float2* __restrict__ bpart)
{
    constexpr int KP = K / 2;
    extern __shared__ char sm[];
    const uint32_t smb = (uint32_t)__cvta_generic_to_shared(sm);
    const uint32_t wsm = smb + WOFF;
    const uint32_t xsm = smb + XOFF;
    const uint32_t mb0 = smb + MBOFF;   // 3 mbarriers, 8B apart

    const int tid   = threadIdx.x;
    const int lane  = tid & 31;
    const int wid   = tid >> 5;         // 0..15
    const int g     = lane >> 2;
    const int tig   = lane & 3;
    const int mwarp = wid >> 1;         // 0..7 -> m base mwarp*32
    const int nwarp = wid & 1;          // 0..1 -> n base nwarp*32

    const int nglob = blockIdx.x * BNCOL;
    const int b     = nglob >> 13;
    const int n2    = nglob & (N2 - 1);

    const uint32_t* Xhb = Xh + (size_t)b * KP * N2 + n2;
    const uint32_t* Xlb = Xl + (size_t)b * KP * N2 + n2;

    if (tid == 0) {
        mbar_init(mb0,      1);
        mbar_init(mb0 + 8,  1);
        mbar_init(mb0 + 16, 1);
    }
    __syncthreads();

    float acc[2][4][4];
    #pragma unroll
    for (int mt = 0; mt < 2; ++mt)
        #pragma unroll
        for (int nt = 0; nt < 4; ++nt)
            #pragma unroll
            for (int r = 0; r < 4; ++r) acc[mt][nt][r] = 0.0f;

    // ldmatrix lane address within a W stage (row stride 80B)
    const int rowoff  = ((lane >> 3) & 1) * 8 + (lane & 7);
    const int wordoff = (lane >> 4) * 4;
    const uint32_t aOff = ((((mwarp*32 + rowoff) * 20) + wordoff) << 2);

    auto load_W = [&](int chunk, int stg) {        // tid==0 only
        mbar_expect_tx(mb0 + stg * 8, W_STAGE);
        bulk_g2s(wsm + stg * W_STAGE, Wimg + (size_t)chunk * (256*40),
                 W_STAGE, mb0 + stg * 8);
    };
    // X tile per stage: 8 kpair rows x 64 u32, hi rows 0..7, lo rows 8..15
    auto load_X = [&](int kp0, int stg) {          // tid<256
        if (tid < 256) {
            const int plane = tid >> 7;            // 0=hi, 1=lo
            const int t2  = tid & 127;
            const int xkr = t2 >> 4;               // 0..7
            const int xn4 = (t2 & 15) * 4;         // u32 quad
            const uint32_t* src = (plane ? Xlb : Xhb) + (size_t)(kp0 + xkr) * N2 + xn4;
            cp_async16(xsm + stg * X_STAGE
                           + (((plane*8 + xkr) * XROW + xn4) << 2), src);
        }
    };

    constexpr int NITER = K / 16;
    #pragma unroll
    for (int p = 0; p < PSTAGES - 1; ++p) {
        if (tid == 0) load_W(p, p);
        load_X(p * 8, p);
        cp_commit();
    }

    int s = 0, ph = 0;
    for (int i = 0; i < NITER; ++i) {
        const int inext = i + PSTAGES - 1;
        const int sN = (s + PSTAGES - 1) % PSTAGES;
        if (inext < NITER) load_X(inext * 8, sN);
        cp_commit();
        cp_wait<PSTAGES - 2>();
        mbar_wait(mb0 + s * 8, (uint32_t)ph);
        __syncthreads();
        if (inext < NITER && tid == 0) load_W(inext, sN);

        const uint32_t aBase = wsm + s * W_STAGE + aOff;
        const uint32_t xbase = xsm + s * X_STAGE;

        // b-fragments: paired LDS.64 over interleaved columns
        // word at permuted col (p16*16 + 2g)   = logical n = p16*16 + g     (nt=2p)
        // word at permuted col (p16*16 + 2g+1) = logical n = p16*16 + 8 + g (nt=2p+1)
        uint32_t bh[4][2], bl[4][2];
        #pragma unroll
        for (int p16 = 0; p16 < 2; ++p16) {
            const int col = nwarp * 32 + p16 * 16 + 2 * g;
            lds64(bh[2*p16][0], bh[2*p16+1][0], xbase + ((tig       * XROW + col) << 2));
            lds64(bh[2*p16][1], bh[2*p16+1][1], xbase + (((tig + 4) * XROW + col) << 2));
            lds64(bl[2*p16][0], bl[2*p16+1][0], xbase + (((8 + tig)     * XROW + col) << 2));
            lds64(bl[2*p16][1], bl[2*p16+1][1], xbase + (((8 + tig + 4) * XROW + col) << 2));
        }

        #pragma unroll
        for (int mt = 0; mt < 2; ++mt) {
            uint32_t ah[4], al[4];
            ldsm_x4(ah, aBase + mt * 1280);        // hi (bytes 0..31 of row)
            ldsm_x4(al, aBase + mt * 1280 + 32);   // lo (bytes 32..63)
            #pragma unroll
            for (int nt = 0; nt < 4; ++nt) {
                mma_bf16(acc[mt][nt], ah, bh[nt]);   // hi*hi
                mma_bf16(acc[mt][nt], ah, bl[nt]);   // hi*lo
                mma_bf16(acc[mt][nt], al, bh[nt]);   // lo*hi
            }
        }
        __syncthreads();
        if (++s == PSTAGES) { s = 0; ph ^= 1; }
    }

    // ---- epilogue: bias add, store, fused per-channel stats ----
    float* part = (float*)sm;   // reuse W stage 0: [nwarp][256][{s,ss}]
    float* ob = out + (size_t)b * MOUT * N2 + n2;
    #pragma unroll
    for (int mt = 0; mt < 2; ++mt) {
        #pragma unroll
        for (int h = 0; h < 2; ++h) {
            const int m  = mwarp * 32 + mt * 16 + h * 8 + g;
            const float bv = bias[m];
            float s2 = 0.0f, ss = 0.0f;
            #pragma unroll
            for (int nt = 0; nt < 4; ++nt) {
                const float v0 = acc[mt][nt][h*2+0] + bv;
                const float v1 = acc[mt][nt][h*2+1] + bv;
                const int n = nwarp * 32 + nt * 8 + 2 * tig;
                *(float2*)(ob + (size_t)m * N2 + n) = make_float2(v0, v1);
                s2 += v0 + v1;
                ss += v0*v0 + v1*v1;
            }
            s2 += __shfl_xor_sync(0xffffffffu, s2, 1);
            s2 += __shfl_xor_sync(0xffffffffu, s2, 2);
            ss += __shfl_xor_sync(0xffffffffu, ss, 1);
            ss += __shfl_xor_sync(0xffffffffu, ss, 2);
            if (tig == 0) {
                part[(nwarp * 256 + m) * 2 + 0] = s2;
                part[(nwarp * 256 + m) * 2 + 1] = ss;
            }
        }
    }
    __syncthreads();
    if (tid < 256) {
        float2 r;
        r.x = part[tid * 2]     + part[(256 + tid) * 2];
        r.y = part[tid * 2 + 1] + part[(256 + tid) * 2 + 1];
        bpart[(size_t)blockIdx.x * MOUT + tid] = r;
    }
}

// ---------------- 4/6) stage-2 stats reduce ---------------------------------
__global__ void stats2_kernel(const float* __restrict__ gamma,
                              const float* __restrict__ beta,
                              float* __restrict__ scale,
                              float* __restrict__ shift)
{
    const int c = blockIdx.x;
    double s = 0.0, ss = 0.0;
    for (int j = threadIdx.x; j < NBLK; j += 256) {
        const float2 p = g_bpart[(size_t)j * MOUT + c];
        s  += (double)p.x;
        ss += (double)p.y;
    }
    __shared__ double rs[256], rss[256];
    rs[threadIdx.x] = s; rss[threadIdx.x] = ss;
    __syncthreads();
    for (int o = 128; o > 0; o >>= 1) {
        if (threadIdx.x < o) {
            rs[threadIdx.x]  += rs[threadIdx.x + o];
            rss[threadIdx.x] += rss[threadIdx.x + o];
        }
        __syncthreads();
    }
    if (threadIdx.x == 0) {
        const double mean = rs[0] / (double)NTOT;
        const double var  = rss[0] / (double)NTOT - mean * mean;
        const float istd  = (float)(1.0 / sqrt(var + 1e-3));
        const float sc    = gamma[c] * istd;
        scale[c] = sc;
        shift[c] = beta[c] - (float)mean * sc;
    }
}

// ---------------- 7) in-place BN+ReLU of layer-2 output ---------------------
__global__ void finalize_kernel(float* __restrict__ out)
{
    const size_t i4 = (size_t)blockIdx.x * blockDim.x + threadIdx.x;
    const int c = (int)((i4 >> 11) & 255);
    float4* p = (float4*)out + i4;
    float4 v = *p;
    const float sc = g_scale2[c], sh = g_shift2[c];
    v.x = fmaxf(fmaf(v.x, sc, sh), 0.0f);
    v.y = fmaxf(fmaf(v.y, sc, sh), 0.0f);
    v.z = fmaxf(fmaf(v.z, sc, sh), 0.0f);
    v.w = fmaxf(fmaf(v.w, sc, sh), 0.0f);
    *p = v;
}

// ---------------- launch ----------------------------------------------------
extern "C" void kernel_launch(void* const* d_in, const int* in_sizes, int n_in,
                              void* d_out, int out_size)
{
    const float* xyz2  = (const float*)d_in[0];
    const float* xyz1  = (const float*)d_in[1];
    const float* feat2 = (const float*)d_in[2];
    const float* feat1 = (const float*)d_in[3];
    const float* W1    = (const float*)d_in[4];
    const float* b1    = (const float*)d_in[5];
    const float* g1    = (const float*)d_in[6];
    const float* be1   = (const float*)d_in[7];
    const float* W2    = (const float*)d_in[8];
    const float* b2    = (const float*)d_in[9];
    const float* g2    = (const float*)d_in[10];
    const float* be2   = (const float*)d_in[11];
    float* out = (float*)d_out;

    float  *p_Y1, *p_s1, *p_sh1, *p_s2, *p_sh2;
    unsigned short *p_W1img, *p_W2img;
    uint32_t *p_X1h, *p_X1l, *p_X2h, *p_X2l;
    float2 *p_bpart;
    cudaGetSymbolAddress((void**)&p_Y1,     g_Y1);
    cudaGetSymbolAddress((void**)&p_s1,     g_scale1);
    cudaGetSymbolAddress((void**)&p_sh1,    g_shift1);
    cudaGetSymbolAddress((void**)&p_s2,     g_scale2);
    cudaGetSymbolAddress((void**)&p_sh2,    g_shift2);
    cudaGetSymbolAddress((void**)&p_bpart,  g_bpart);
    cudaGetSymbolAddress((void**)&p_W1img,  g_W1img);
    cudaGetSymbolAddress((void**)&p_W2img,  g_W2img);
    cudaGetSymbolAddress((void**)&p_X1h,    g_X1h);
    cudaGetSymbolAddress((void**)&p_X1l,    g_X1l);
    cudaGetSymbolAddress((void**)&p_X2h,    g_X2h);
    cudaGetSymbolAddress((void**)&p_X2l,    g_X2l);

    static int attr_done = 0;
    if (!attr_done) {
        cudaFuncSetAttribute(gemm_tc_kernel<CIN>,
                             cudaFuncAttributeMaxDynamicSharedMemorySize, SMEM_DYN);
        cudaFuncSetAttribute(gemm_tc_kernel<MOUT>,
                             cudaFuncAttributeMaxDynamicSharedMemorySize, SMEM_DYN);
        attr_done = 1;
    }

    knn_kernel<<<dim3(N2/256, BB), 256>>>(xyz2, xyz1);
    buildX1_kernel<<<dim3(N2/256, BB), 256>>>(feat1, feat2);
    prep_wimg_kernel<<<(WCH1*256 + 255)/256, 256>>>(W1, W2);

    // layer 1: y1 = W1 @ [interp; feat2] + b1 (raw) + fused stats partials
    gemm_tc_kernel<CIN><<<NBLK, 512, SMEM_DYN>>>(
        p_W1img, b1, p_X1h, p_X1l, p_Y1, p_bpart);
    stats2_kernel<<<MOUT, 256>>>(g1, be1, p_s1, p_sh1);

    convY_kernel<<<dim3(N2/256, MOUT/2, BB), 256>>>();

    // layer 2: y2 = W2 @ relu(bn(y1)) + b2 -> d_out (raw) + fused stats
    gemm_tc_kernel<MOUT><<<NBLK, 512, SMEM_DYN>>>(
        p_W2img, b2, p_X2h, p_X2l, out, p_bpart);
    stats2_kernel<<<MOUT, 256>>>(g2, be2, p_s2, p_sh2);

    finalize_kernel<<<(NTOT * MOUT / 4) / 256, 256>>>(out);
}